// round 3
// baseline (speedup 1.0000x reference)
#include <cuda_runtime.h>
#include <cuda_bf16.h>

// Problem constants
#define B_ 4
#define T_ 2048
#define C_ 1024
#define H_ 16
#define D_ 64
#define BT (B_*T_)          // 8192
#define F3 (3*C_)           // 3072

// Scratch (static device allocations — no cudaMalloc allowed)
__device__ float g_qkv[(size_t)BT * F3];   // [8192, 3072]
__device__ float g_att[(size_t)BT * C_];   // [8192, 1024]

// ============================================================================
// Tensor-core GEMM with 3xBF16 split: C[M,N] = A[M,K] @ B[N,K]^T (fp32 I/O).
// Each fp32 operand x = hi + lo (bf16 each); D += Ahi*Bhi + Ahi*Blo + Alo*Bhi.
// Per-product error ~2^-17 -> fp32-grade accuracy on tensor cores.
//
// CTA tile 128x128, K-slice 32. 8 warps in 2(m) x 4(n); warp tile 64x32 as
// 4x4 grid of mma.m16n8k16 fragments. Smem: 4 bf16 planes, row stride 20 u32
// (16 data + 4 pad) -> fragment loads are bank-conflict-free.
// Double-buffered smem + register-staged global prefetch.
// ============================================================================
#define GBM 128
#define GBN 128
#define GBK 32
#define SROW 20             // u32 words per smem row
#define PS   (128*SROW)     // plane size in u32 (2560)
#define GEMM_SMEM (2*4*PS*4)  // 2 buffers * 4 planes * PS u32 * 4B = 81920 B

__device__ __forceinline__ void mma_bf16_16816(float* d, const unsigned* a,
                                               const unsigned* b, const float* c)
{
    asm volatile(
        "mma.sync.aligned.m16n8k16.row.col.f32.bf16.bf16.f32 "
        "{%0,%1,%2,%3}, {%4,%5,%6,%7}, {%8,%9}, {%10,%11,%12,%13};\n"
        : "=f"(d[0]), "=f"(d[1]), "=f"(d[2]), "=f"(d[3])
        : "r"(a[0]), "r"(a[1]), "r"(a[2]), "r"(a[3]),
          "r"(b[0]), "r"(b[1]),
          "f"(c[0]), "f"(c[1]), "f"(c[2]), "f"(c[3]));
}

// Split two fp32 into bf16 hi/lo pairs and store packed words to the planes.
__device__ __forceinline__ void cvt_store(unsigned* hiP, unsigned* loP, int word,
                                          float x0, float x1)
{
    __nv_bfloat16 h0 = __float2bfloat16_rn(x0);
    __nv_bfloat16 h1 = __float2bfloat16_rn(x1);
    float l0 = x0 - __bfloat162float(h0);
    float l1 = x1 - __bfloat162float(h1);
    __nv_bfloat162 hv; hv.x = h0; hv.y = h1;
    __nv_bfloat162 lv; lv.x = __float2bfloat16_rn(l0); lv.y = __float2bfloat16_rn(l1);
    hiP[word] = *(unsigned*)&hv;
    loP[word] = *(unsigned*)&lv;
}

__global__ __launch_bounds__(256, 1)
void gemm_bf16split(const float* __restrict__ A, const float* __restrict__ Bm,
                    float* __restrict__ C, int M, int N, int K)
{
    extern __shared__ unsigned sm_u[];

    const int tid  = threadIdx.x;
    const int lane = tid & 31;
    const int wid  = tid >> 5;
    const int wm   = (wid >> 2) * 64;   // warp m-offset within CTA tile
    const int wn   = (wid & 3) * 32;    // warp n-offset
    const int m0   = blockIdx.y * GBM;
    const int n0   = blockIdx.x * GBN;

    // Global-load coords: 4 float4 per matrix per K-slice per thread.
    const int grow = tid >> 3;          // 0..31 (+ i*32)
    const int gc4  = (tid & 7) * 4;     // 0,4,...,28
    const float* Ag = A  + (size_t)(m0 + grow) * K + gc4;
    const float* Bg = Bm + (size_t)(n0 + grow) * K + gc4;

    float acc[4][4][4];
#pragma unroll
    for (int i = 0; i < 4; i++)
#pragma unroll
        for (int j = 0; j < 4; j++)
#pragma unroll
            for (int r = 0; r < 4; r++) acc[i][j][r] = 0.f;

    // Prologue: fill buffer 0 with slice 0
#pragma unroll
    for (int i = 0; i < 4; i++) {
        float4 av = *(const float4*)(Ag + (size_t)i * 32 * K);
        float4 bv = *(const float4*)(Bg + (size_t)i * 32 * K);
        int word = (grow + i * 32) * SROW + (gc4 >> 1);
        cvt_store(sm_u + 0*PS, sm_u + 1*PS, word,     av.x, av.y);
        cvt_store(sm_u + 0*PS, sm_u + 1*PS, word + 1, av.z, av.w);
        cvt_store(sm_u + 2*PS, sm_u + 3*PS, word,     bv.x, bv.y);
        cvt_store(sm_u + 2*PS, sm_u + 3*PS, word + 1, bv.z, bv.w);
    }
    __syncthreads();

    const int r4  = lane >> 2;  // 0..7
    const int c4b = lane & 3;   // 0..3

    int buf = 0;
    const int NS = K / GBK;
    for (int s = 0; s < NS; s++) {
        const bool more = (s + 1) < NS;
        float4 pa[4], pb[4];
        if (more) {
            const int kn = (s + 1) * GBK;
#pragma unroll
            for (int i = 0; i < 4; i++) {
                pa[i] = *(const float4*)(Ag + (size_t)i * 32 * K + kn);
                pb[i] = *(const float4*)(Bg + (size_t)i * 32 * K + kn);
            }
        }

        const unsigned* AH = sm_u + (buf * 4 + 0) * PS;
        const unsigned* AL = sm_u + (buf * 4 + 1) * PS;
        const unsigned* BH = sm_u + (buf * 4 + 2) * PS;
        const unsigned* BL = sm_u + (buf * 4 + 3) * PS;

#pragma unroll
        for (int ks = 0; ks < 2; ks++) {
            unsigned ah[4][4], al[4][4], bh[4][2], bl[4][2];
#pragma unroll
            for (int mt = 0; mt < 4; mt++) {
                int w = (wm + mt * 16 + r4) * SROW + ks * 8 + c4b;
                ah[mt][0] = AH[w];            ah[mt][1] = AH[w + 8*SROW];
                ah[mt][2] = AH[w + 4];        ah[mt][3] = AH[w + 8*SROW + 4];
                al[mt][0] = AL[w];            al[mt][1] = AL[w + 8*SROW];
                al[mt][2] = AL[w + 4];        al[mt][3] = AL[w + 8*SROW + 4];
            }
#pragma unroll
            for (int nt = 0; nt < 4; nt++) {
                int w = (wn + nt * 8 + r4) * SROW + ks * 8 + c4b;
                bh[nt][0] = BH[w];  bh[nt][1] = BH[w + 4];
                bl[nt][0] = BL[w];  bl[nt][1] = BL[w + 4];
            }
#pragma unroll
            for (int mt = 0; mt < 4; mt++)
#pragma unroll
                for (int nt = 0; nt < 4; nt++) {
                    mma_bf16_16816(acc[mt][nt], ah[mt], bh[nt], acc[mt][nt]);
                    mma_bf16_16816(acc[mt][nt], ah[mt], bl[nt], acc[mt][nt]);
                    mma_bf16_16816(acc[mt][nt], al[mt], bh[nt], acc[mt][nt]);
                }
        }

        if (more) {
            const int nb = buf ^ 1;
            unsigned* nAH = sm_u + (nb * 4 + 0) * PS;
            unsigned* nAL = sm_u + (nb * 4 + 1) * PS;
            unsigned* nBH = sm_u + (nb * 4 + 2) * PS;
            unsigned* nBL = sm_u + (nb * 4 + 3) * PS;
#pragma unroll
            for (int i = 0; i < 4; i++) {
                int word = (grow + i * 32) * SROW + (gc4 >> 1);
                cvt_store(nAH, nAL, word,     pa[i].x, pa[i].y);
                cvt_store(nAH, nAL, word + 1, pa[i].z, pa[i].w);
                cvt_store(nBH, nBL, word,     pb[i].x, pb[i].y);
                cvt_store(nBH, nBL, word + 1, pb[i].z, pb[i].w);
            }
            __syncthreads();
        }
        buf ^= 1;
    }

    // Epilogue: c0/c1 at (row, 2c),(row, 2c+1); c2/c3 at row+8.
#pragma unroll
    for (int mt = 0; mt < 4; mt++) {
        int row0 = m0 + wm + mt * 16 + r4;
#pragma unroll
        for (int nt = 0; nt < 4; nt++) {
            int col = n0 + wn + nt * 8 + c4b * 2;
            *(float2*)(C + (size_t)row0 * N + col) =
                make_float2(acc[mt][nt][0], acc[mt][nt][1]);
            *(float2*)(C + (size_t)(row0 + 8) * N + col) =
                make_float2(acc[mt][nt][2], acc[mt][nt][3]);
        }
    }
}

// ----------------------------------------------------------------------------
// Fused causal flash attention, fp32 SIMT (unchanged from R1).
// Grid: (T/64, H, B). Block: 256 threads (16x16).
// ----------------------------------------------------------------------------
#define PAD 68   // row stride in floats for 64-wide smem tiles

__global__ __launch_bounds__(256, 3)
void flash_attn(const float* __restrict__ qkv, float* __restrict__ att)
{
    extern __shared__ float sm[];
    float* Qs  = sm;                 // [64][PAD]  row-major (scaled Q)
    float* KsT = Qs  + 64 * PAD;     // [64][PAD]  d-major: KsT[d*PAD + j]
    float* Vs  = KsT + 64 * PAD;     // [64][PAD]  j-major: Vs[j*PAD + d]
    float* Ps  = Vs  + 64 * PAD;     // [64][PAD]  i-major: Ps[i*PAD + j]

    const int qt = blockIdx.x, h = blockIdx.y, b = blockIdx.z;
    const int tid = threadIdx.x;
    const int tx = tid & 15, ty = tid >> 4;

    const float scale = 0.125f;  // 1/sqrt(64)
    const size_t base = (size_t)b * T_ * F3;
    const float* Qg = qkv + base + (size_t)(qt * 64) * F3 + h * D_;

#pragma unroll
    for (int it = 0; it < 4; it++) {
        int lin = tid + it * 256;
        int row = lin >> 4, c4 = (lin & 15) * 4;
        float4 v = *(const float4*)(Qg + (size_t)row * F3 + c4);
        float* dst = Qs + row * PAD + c4;
        dst[0] = v.x * scale; dst[1] = v.y * scale;
        dst[2] = v.z * scale; dst[3] = v.w * scale;
    }

    float m[4], l[4], o[4][4];
#pragma unroll
    for (int i = 0; i < 4; i++) {
        m[i] = -1e30f; l[i] = 0.f;
#pragma unroll
        for (int j = 0; j < 4; j++) o[i][j] = 0.f;
    }

    for (int kt = 0; kt <= qt; kt++) {
        const float* Kg = qkv + base + (size_t)(kt * 64) * F3 + C_  + h * D_;
        const float* Vg = qkv + base + (size_t)(kt * 64) * F3 + 2*C_ + h * D_;

        __syncthreads();
#pragma unroll
        for (int it = 0; it < 4; it++) {
            int lin = tid + it * 256;
            int row = lin >> 4, c4 = (lin & 15) * 4;
            float4 kv = *(const float4*)(Kg + (size_t)row * F3 + c4);
            KsT[(c4 + 0) * PAD + row] = kv.x;
            KsT[(c4 + 1) * PAD + row] = kv.y;
            KsT[(c4 + 2) * PAD + row] = kv.z;
            KsT[(c4 + 3) * PAD + row] = kv.w;
            float4 vv = *(const float4*)(Vg + (size_t)row * F3 + c4);
            *(float4*)(Vs + row * PAD + c4) = vv;
        }
        __syncthreads();

        float s[4][4];
#pragma unroll
        for (int i = 0; i < 4; i++)
#pragma unroll
            for (int j = 0; j < 4; j++) s[i][j] = 0.f;

#pragma unroll 4
        for (int d = 0; d < 64; d++) {
            float a[4];
#pragma unroll
            for (int i = 0; i < 4; i++) a[i] = Qs[(ty * 4 + i) * PAD + d];
            float4 bv = *(const float4*)(KsT + d * PAD + tx * 4);
            float bb[4] = {bv.x, bv.y, bv.z, bv.w};
#pragma unroll
            for (int i = 0; i < 4; i++)
#pragma unroll
                for (int j = 0; j < 4; j++)
                    s[i][j] = fmaf(a[i], bb[j], s[i][j]);
        }

        if (kt == qt) {
#pragma unroll
            for (int i = 0; i < 4; i++)
#pragma unroll
                for (int j = 0; j < 4; j++)
                    if (tx * 4 + j > ty * 4 + i) s[i][j] = -1e30f;
        }

#pragma unroll
        for (int i = 0; i < 4; i++) {
            float mx = fmaxf(fmaxf(s[i][0], s[i][1]), fmaxf(s[i][2], s[i][3]));
#pragma unroll
            for (int off = 1; off < 16; off <<= 1)
                mx = fmaxf(mx, __shfl_xor_sync(0xffffffffu, mx, off));
            float mn = fmaxf(m[i], mx);
            float corr = __expf(m[i] - mn);
            m[i] = mn;
            float ssum = 0.f;
#pragma unroll
            for (int j = 0; j < 4; j++) {
                float p = __expf(s[i][j] - mn);
                s[i][j] = p;
                ssum += p;
            }
#pragma unroll
            for (int off = 1; off < 16; off <<= 1)
                ssum += __shfl_xor_sync(0xffffffffu, ssum, off);
            l[i] = l[i] * corr + ssum;
#pragma unroll
            for (int j = 0; j < 4; j++) o[i][j] *= corr;
            *(float4*)(Ps + (ty * 4 + i) * PAD + tx * 4) =
                make_float4(s[i][0], s[i][1], s[i][2], s[i][3]);
        }
        __syncthreads();

#pragma unroll 4
        for (int j = 0; j < 64; j++) {
            float a[4];
#pragma unroll
            for (int i = 0; i < 4; i++) a[i] = Ps[(ty * 4 + i) * PAD + j];
            float4 bv = *(const float4*)(Vs + j * PAD + tx * 4);
            float bb[4] = {bv.x, bv.y, bv.z, bv.w};
#pragma unroll
            for (int i = 0; i < 4; i++)
#pragma unroll
                for (int jj = 0; jj < 4; jj++)
                    o[i][jj] = fmaf(a[i], bb[jj], o[i][jj]);
        }
    }

    const size_t orow0 = (size_t)b * T_ + qt * 64;
#pragma unroll
    for (int i = 0; i < 4; i++) {
        float inv = 1.f / l[i];
        float4 r = make_float4(o[i][0] * inv, o[i][1] * inv,
                               o[i][2] * inv, o[i][3] * inv);
        *(float4*)(att + (orow0 + ty * 4 + i) * C_ + h * D_ + tx * 4) = r;
    }
}

// ----------------------------------------------------------------------------
// Launch
// ----------------------------------------------------------------------------
extern "C" void kernel_launch(void* const* d_in, const int* in_sizes, int n_in,
                              void* d_out, int out_size)
{
    const float* x     = (const float*)d_in[0];
    // d_in[1] = causal mask (bool) — causality applied analytically, unused
    const float* w_qkv = (const float*)d_in[2];
    const float* w_out = (const float*)d_in[3];
    float* out = (float*)d_out;

    float* qkv_ptr; float* att_ptr;
    cudaGetSymbolAddress((void**)&qkv_ptr, g_qkv);
    cudaGetSymbolAddress((void**)&att_ptr, g_att);

    static const int FLASH_SMEM = 4 * 64 * PAD * sizeof(float);  // 69,632 B
    cudaFuncSetAttribute(flash_attn,
                         cudaFuncAttributeMaxDynamicSharedMemorySize, FLASH_SMEM);
    cudaFuncSetAttribute(gemm_bf16split,
                         cudaFuncAttributeMaxDynamicSharedMemorySize, GEMM_SMEM);

    // 1) QKV projection: [8192,3072] = x[8192,1024] @ w_qkv[3072,1024]^T
    {
        dim3 grid(F3 / GBN, BT / GBM);
        gemm_bf16split<<<grid, 256, GEMM_SMEM>>>(x, w_qkv, qkv_ptr, BT, F3, C_);
    }

    // 2) Fused causal attention -> g_att [8192,1024] (heads merged)
    {
        dim3 grid(T_ / 64, H_, B_);
        flash_attn<<<grid, 256, FLASH_SMEM>>>(qkv_ptr, att_ptr);
    }

    // 3) Output projection: out[8192,1024] = att @ w_out[1024,1024]^T
    {
        dim3 grid(C_ / GBN, BT / GBM);
        gemm_bf16split<<<grid, 256, GEMM_SMEM>>>(att_ptr, w_out, out, BT, C_, C_);
    }
}

// round 5
// speedup vs baseline: 1.7234x; 1.7234x over previous
#include <cuda_runtime.h>
#include <cuda_bf16.h>

// Problem constants
#define B_ 4
#define T_ 2048
#define C_ 1024
#define H_ 16
#define D_ 64
#define BT (B_*T_)          // 8192
#define F3 (3*C_)           // 3072

// Scratch (static device allocations — no cudaMalloc allowed)
__device__ float g_qkv[(size_t)BT * F3];   // [8192, 3072]
__device__ float g_att[(size_t)BT * C_];   // [8192, 1024]

// ============================================================================
// Common helpers
// ============================================================================
__device__ __forceinline__ void mma_bf16_16816(float* d, const unsigned* a,
                                               const unsigned* b, const float* c)
{
    asm volatile(
        "mma.sync.aligned.m16n8k16.row.col.f32.bf16.bf16.f32 "
        "{%0,%1,%2,%3}, {%4,%5,%6,%7}, {%8,%9}, {%10,%11,%12,%13};\n"
        : "=f"(d[0]), "=f"(d[1]), "=f"(d[2]), "=f"(d[3])
        : "r"(a[0]), "r"(a[1]), "r"(a[2]), "r"(a[3]),
          "r"(b[0]), "r"(b[1]),
          "f"(c[0]), "f"(c[1]), "f"(c[2]), "f"(c[3]));
}

__device__ __forceinline__ unsigned pack_bf16(float x0, float x1)
{
    __nv_bfloat162 t = __floats2bfloat162_rn(x0, x1);  // x0 -> low half
    return *(unsigned*)&t;
}

// Split two fp32 into (hi,lo) packed bf16x2 words.
__device__ __forceinline__ void split2(float x0, float x1, unsigned& hi, unsigned& lo)
{
    __nv_bfloat16 h0 = __float2bfloat16_rn(x0);
    __nv_bfloat16 h1 = __float2bfloat16_rn(x1);
    __nv_bfloat162 hv; hv.x = h0; hv.y = h1;
    hi = *(unsigned*)&hv;
    lo = pack_bf16(x0 - __bfloat162float(h0), x1 - __bfloat162float(h1));
}

__device__ __forceinline__ unsigned smem_u32(const void* p)
{
    unsigned a;
    asm("{ .reg .u64 t; cvta.to.shared.u64 t, %1; cvt.u32.u64 %0, t; }"
        : "=r"(a) : "l"(p));
    return a;
}

// ============================================================================
// Tensor-core GEMM with 3xBF16 split. Term-major HMMA ordering: each of the
// three split terms is issued over all 16 independent tiles before the next
// term touches the same accumulator -> dependent-pair distance 16 instrs.
// ============================================================================
#define GBM 128
#define GBN 128
#define GBK 32
#define SROW 20
#define PS   (128*SROW)
#define GEMM_SMEM (2*4*PS*4)

__device__ __forceinline__ void cvt_store(unsigned* hiP, unsigned* loP, int word,
                                          float x0, float x1)
{
    unsigned h, l;
    split2(x0, x1, h, l);
    hiP[word] = h;
    loP[word] = l;
}

__global__ __launch_bounds__(256, 1)
void gemm_bf16split(const float* __restrict__ A, const float* __restrict__ Bm,
                    float* __restrict__ C, int M, int N, int K)
{
    extern __shared__ unsigned sm_u[];

    const int tid  = threadIdx.x;
    const int lane = tid & 31;
    const int wid  = tid >> 5;
    const int wm   = (wid >> 2) * 64;
    const int wn   = (wid & 3) * 32;
    const int m0   = blockIdx.y * GBM;
    const int n0   = blockIdx.x * GBN;

    const int grow = tid >> 3;
    const int gc4  = (tid & 7) * 4;
    const float* Ag = A  + (size_t)(m0 + grow) * K + gc4;
    const float* Bg = Bm + (size_t)(n0 + grow) * K + gc4;

    float acc[4][4][4];
#pragma unroll
    for (int i = 0; i < 4; i++)
#pragma unroll
        for (int j = 0; j < 4; j++)
#pragma unroll
            for (int r = 0; r < 4; r++) acc[i][j][r] = 0.f;

#pragma unroll
    for (int i = 0; i < 4; i++) {
        float4 av = *(const float4*)(Ag + (size_t)i * 32 * K);
        float4 bv = *(const float4*)(Bg + (size_t)i * 32 * K);
        int word = (grow + i * 32) * SROW + (gc4 >> 1);
        cvt_store(sm_u + 0*PS, sm_u + 1*PS, word,     av.x, av.y);
        cvt_store(sm_u + 0*PS, sm_u + 1*PS, word + 1, av.z, av.w);
        cvt_store(sm_u + 2*PS, sm_u + 3*PS, word,     bv.x, bv.y);
        cvt_store(sm_u + 2*PS, sm_u + 3*PS, word + 1, bv.z, bv.w);
    }
    __syncthreads();

    const int r4  = lane >> 2;
    const int c4b = lane & 3;

    int buf = 0;
    const int NS = K / GBK;
    for (int s = 0; s < NS; s++) {
        const bool more = (s + 1) < NS;
        float4 pa[4], pb[4];
        if (more) {
            const int kn = (s + 1) * GBK;
#pragma unroll
            for (int i = 0; i < 4; i++) {
                pa[i] = *(const float4*)(Ag + (size_t)i * 32 * K + kn);
                pb[i] = *(const float4*)(Bg + (size_t)i * 32 * K + kn);
            }
        }

        const unsigned* AH = sm_u + (buf * 4 + 0) * PS;
        const unsigned* AL = sm_u + (buf * 4 + 1) * PS;
        const unsigned* BH = sm_u + (buf * 4 + 2) * PS;
        const unsigned* BL = sm_u + (buf * 4 + 3) * PS;

#pragma unroll
        for (int ks = 0; ks < 2; ks++) {
            unsigned ah[4][4], al[4][4], bh[4][2], bl[4][2];
#pragma unroll
            for (int mt = 0; mt < 4; mt++) {
                int w = (wm + mt * 16 + r4) * SROW + ks * 8 + c4b;
                ah[mt][0] = AH[w];            ah[mt][1] = AH[w + 8*SROW];
                ah[mt][2] = AH[w + 4];        ah[mt][3] = AH[w + 8*SROW + 4];
                al[mt][0] = AL[w];            al[mt][1] = AL[w + 8*SROW];
                al[mt][2] = AL[w + 4];        al[mt][3] = AL[w + 8*SROW + 4];
            }
#pragma unroll
            for (int nt = 0; nt < 4; nt++) {
                int w = (wn + nt * 8 + r4) * SROW + ks * 8 + c4b;
                bh[nt][0] = BH[w];  bh[nt][1] = BH[w + 4];
                bl[nt][0] = BL[w];  bl[nt][1] = BL[w + 4];
            }
            // Term-major: all tiles per split term (16-instr dep distance)
#pragma unroll
            for (int mt = 0; mt < 4; mt++)
#pragma unroll
                for (int nt = 0; nt < 4; nt++)
                    mma_bf16_16816(acc[mt][nt], ah[mt], bh[nt], acc[mt][nt]);
#pragma unroll
            for (int mt = 0; mt < 4; mt++)
#pragma unroll
                for (int nt = 0; nt < 4; nt++)
                    mma_bf16_16816(acc[mt][nt], ah[mt], bl[nt], acc[mt][nt]);
#pragma unroll
            for (int mt = 0; mt < 4; mt++)
#pragma unroll
                for (int nt = 0; nt < 4; nt++)
                    mma_bf16_16816(acc[mt][nt], al[mt], bh[nt], acc[mt][nt]);
        }

        if (more) {
            const int nb = buf ^ 1;
            unsigned* nAH = sm_u + (nb * 4 + 0) * PS;
            unsigned* nAL = sm_u + (nb * 4 + 1) * PS;
            unsigned* nBH = sm_u + (nb * 4 + 2) * PS;
            unsigned* nBL = sm_u + (nb * 4 + 3) * PS;
#pragma unroll
            for (int i = 0; i < 4; i++) {
                int word = (grow + i * 32) * SROW + (gc4 >> 1);
                cvt_store(nAH, nAL, word,     pa[i].x, pa[i].y);
                cvt_store(nAH, nAL, word + 1, pa[i].z, pa[i].w);
                cvt_store(nBH, nBL, word,     pb[i].x, pb[i].y);
                cvt_store(nBH, nBL, word + 1, pb[i].z, pb[i].w);
            }
            __syncthreads();
        }
        buf ^= 1;
    }

#pragma unroll
    for (int mt = 0; mt < 4; mt++) {
        int row0 = m0 + wm + mt * 16 + r4;
#pragma unroll
        for (int nt = 0; nt < 4; nt++) {
            int col = n0 + wn + nt * 8 + c4b * 2;
            *(float2*)(C + (size_t)row0 * N + col) =
                make_float2(acc[mt][nt][0], acc[mt][nt][1]);
            *(float2*)(C + (size_t)(row0 + 8) * N + col) =
                make_float2(acc[mt][nt][2], acc[mt][nt][3]);
        }
    }
}

// ============================================================================
// Tensor-core causal flash attention, 3xBF16 split, term-major mma ordering.
// Block: 128 threads (4 warps). 64 queries x D=64; key tiles of 64.
// ============================================================================
#define FQ2 0                     // uint2 units
#define FK2 (64*36)
#define FVH (2*(FK2 + 64*36))     // u32 units from here
#define FVL (FVH + 64*36)
#define FLASH_SMEM ((2*2*64*36 + 2*64*36) * 4)   // 55296 B

__global__ __launch_bounds__(128, 2)
void flash_attn_tc(const float* __restrict__ qkv, float* __restrict__ att)
{
    extern __shared__ unsigned smf[];
    uint2*    Q2 = (uint2*)smf + FQ2;
    uint2*    K2 = (uint2*)smf + FK2;
    unsigned* Vh = smf + FVH;
    unsigned* Vl = smf + FVL;

    const int qt = 31 - blockIdx.x;       // heavy tiles first
    const int h  = blockIdx.y, b = blockIdx.z;
    const int tid  = threadIdx.x;
    const int lane = tid & 31;
    const int wid  = tid >> 5;
    const int w16  = wid * 16;
    const int r4   = lane >> 2;
    const int t4   = lane & 3;

    const float qscale = 0.125f * 1.44269504088896340736f;  // 1/sqrt(D) * log2(e)
    const size_t base = (size_t)b * T_ * F3;
    const float* Qg = qkv + base + (size_t)(qt * 64) * F3 + h * D_;

    // --- Load + scale + split Q tile (64x64) into interleaved smem ---
#pragma unroll
    for (int it = 0; it < 8; it++) {
        int idx = tid + it * 128;
        int row = idx >> 4, c4 = idx & 15;
        float4 v = *(const float4*)(Qg + (size_t)row * F3 + c4 * 4);
        unsigned h01, l01, h23, l23;
        split2(v.x * qscale, v.y * qscale, h01, l01);
        split2(v.z * qscale, v.w * qscale, h23, l23);
        Q2[row * 36 + 2 * c4    ] = make_uint2(h01, l01);
        Q2[row * 36 + 2 * c4 + 1] = make_uint2(h23, l23);
    }
    __syncthreads();

    // --- Hoist Q fragments into registers (loop-invariant) ---
    unsigned qh[4][4], ql[4][4];
#pragma unroll
    for (int ks = 0; ks < 4; ks++) {
        int w = (w16 + r4) * 36 + ks * 8 + t4;
        uint2 w0 = Q2[w];            qh[ks][0] = w0.x; ql[ks][0] = w0.y;
        uint2 w1 = Q2[w + 8 * 36];   qh[ks][1] = w1.x; ql[ks][1] = w1.y;
        uint2 w2 = Q2[w + 4];        qh[ks][2] = w2.x; ql[ks][2] = w2.y;
        uint2 w3 = Q2[w + 8*36 + 4]; qh[ks][3] = w3.x; ql[ks][3] = w3.y;
    }

    const unsigned vh_base = smem_u32(Vh) + (lane & 15) * 144;
    const unsigned vl_base = smem_u32(Vl) + (lane & 15) * 144;

    float m0 = -1e30f, m1 = -1e30f, l0 = 0.f, l1 = 0.f;
    float o[8][4];
#pragma unroll
    for (int nd = 0; nd < 8; nd++)
#pragma unroll
        for (int e = 0; e < 4; e++) o[nd][e] = 0.f;

    const int qrow0 = qt * 64 + w16 + r4;
    const int qrow1 = qrow0 + 8;

    for (int kt = 0; kt <= qt; kt++) {
        const float* Kg = qkv + base + (size_t)(kt * 64) * F3 + C_   + h * D_;
        const float* Vg = qkv + base + (size_t)(kt * 64) * F3 + 2*C_ + h * D_;

        __syncthreads();
#pragma unroll
        for (int it = 0; it < 8; it++) {
            int idx = tid + it * 128;
            int row = idx >> 4, c4 = idx & 15;
            float4 kv = *(const float4*)(Kg + (size_t)row * F3 + c4 * 4);
            unsigned h01, l01, h23, l23;
            split2(kv.x, kv.y, h01, l01);
            split2(kv.z, kv.w, h23, l23);
            K2[row * 36 + 2 * c4    ] = make_uint2(h01, l01);
            K2[row * 36 + 2 * c4 + 1] = make_uint2(h23, l23);
            float4 vv = *(const float4*)(Vg + (size_t)row * F3 + c4 * 4);
            unsigned vh01, vl01, vh23, vl23;
            split2(vv.x, vv.y, vh01, vl01);
            split2(vv.z, vv.w, vh23, vl23);
            *(uint2*)(Vh + row * 36 + 2 * c4) = make_uint2(vh01, vh23);
            *(uint2*)(Vl + row * 36 + 2 * c4) = make_uint2(vl01, vl23);
        }
        __syncthreads();

        // --- S = Q K^T (3-term split, term-major per ks) ---
        float s[8][4];
#pragma unroll
        for (int j = 0; j < 8; j++)
#pragma unroll
            for (int e = 0; e < 4; e++) s[j][e] = 0.f;

#pragma unroll
        for (int ks = 0; ks < 4; ks++) {
            unsigned bh[8][2], bl[8][2];
#pragma unroll
            for (int j = 0; j < 8; j++) {
                int w = (j * 8 + r4) * 36 + ks * 8 + t4;
                uint2 w0 = K2[w];
                uint2 w1 = K2[w + 4];
                bh[j][0] = w0.x; bh[j][1] = w1.x;
                bl[j][0] = w0.y; bl[j][1] = w1.y;
            }
#pragma unroll
            for (int j = 0; j < 8; j++)
                mma_bf16_16816(s[j], qh[ks], bh[j], s[j]);
#pragma unroll
            for (int j = 0; j < 8; j++)
                mma_bf16_16816(s[j], qh[ks], bl[j], s[j]);
#pragma unroll
            for (int j = 0; j < 8; j++)
                mma_bf16_16816(s[j], ql[ks], bh[j], s[j]);
        }

        // --- Causal mask (diagonal tile only) ---
        if (kt == qt) {
#pragma unroll
            for (int j = 0; j < 8; j++) {
                int kc = kt * 64 + j * 8 + 2 * t4;
                if (kc     > qrow0) s[j][0] = -1e30f;
                if (kc + 1 > qrow0) s[j][1] = -1e30f;
                if (kc     > qrow1) s[j][2] = -1e30f;
                if (kc + 1 > qrow1) s[j][3] = -1e30f;
            }
        }

        // --- Online softmax (exp2 domain) ---
        float mx0 = -1e30f, mx1 = -1e30f;
#pragma unroll
        for (int j = 0; j < 8; j++) {
            mx0 = fmaxf(mx0, fmaxf(s[j][0], s[j][1]));
            mx1 = fmaxf(mx1, fmaxf(s[j][2], s[j][3]));
        }
        mx0 = fmaxf(mx0, __shfl_xor_sync(0xffffffffu, mx0, 1));
        mx0 = fmaxf(mx0, __shfl_xor_sync(0xffffffffu, mx0, 2));
        mx1 = fmaxf(mx1, __shfl_xor_sync(0xffffffffu, mx1, 1));
        mx1 = fmaxf(mx1, __shfl_xor_sync(0xffffffffu, mx1, 2));

        float nm0 = fmaxf(m0, mx0), nm1 = fmaxf(m1, mx1);
        float c0 = exp2f(m0 - nm0), c1 = exp2f(m1 - nm1);
        m0 = nm0; m1 = nm1;

        float sum0 = 0.f, sum1 = 0.f;
#pragma unroll
        for (int j = 0; j < 8; j++) {
            s[j][0] = exp2f(s[j][0] - m0);
            s[j][1] = exp2f(s[j][1] - m0);
            s[j][2] = exp2f(s[j][2] - m1);
            s[j][3] = exp2f(s[j][3] - m1);
            sum0 += s[j][0] + s[j][1];
            sum1 += s[j][2] + s[j][3];
        }
        sum0 += __shfl_xor_sync(0xffffffffu, sum0, 1);
        sum0 += __shfl_xor_sync(0xffffffffu, sum0, 2);
        sum1 += __shfl_xor_sync(0xffffffffu, sum1, 1);
        sum1 += __shfl_xor_sync(0xffffffffu, sum1, 2);
        l0 = l0 * c0 + sum0;
        l1 = l1 * c1 + sum1;

#pragma unroll
        for (int nd = 0; nd < 8; nd++) {
            o[nd][0] *= c0; o[nd][1] *= c0;
            o[nd][2] *= c1; o[nd][3] *= c1;
        }

        // --- O += P V (3-term split, term-major per kp) ---
#pragma unroll
        for (int kp = 0; kp < 4; kp++) {
            const int j0 = 2 * kp, j1 = 2 * kp + 1;
            unsigned ph[4], pl[4];
            split2(s[j0][0], s[j0][1], ph[0], pl[0]);
            split2(s[j0][2], s[j0][3], ph[1], pl[1]);
            split2(s[j1][0], s[j1][1], ph[2], pl[2]);
            split2(s[j1][2], s[j1][3], ph[3], pl[3]);

            unsigned vbh[8][2], vbl[8][2];
#pragma unroll
            for (int nd = 0; nd < 8; nd++) {
                asm volatile("ldmatrix.sync.aligned.m8n8.x2.trans.shared.b16 {%0,%1}, [%2];"
                             : "=r"(vbh[nd][0]), "=r"(vbh[nd][1])
                             : "r"(vh_base + kp * 16 * 144 + nd * 16));
                asm volatile("ldmatrix.sync.aligned.m8n8.x2.trans.shared.b16 {%0,%1}, [%2];"
                             : "=r"(vbl[nd][0]), "=r"(vbl[nd][1])
                             : "r"(vl_base + kp * 16 * 144 + nd * 16));
            }
#pragma unroll
            for (int nd = 0; nd < 8; nd++)
                mma_bf16_16816(o[nd], ph, vbh[nd], o[nd]);
#pragma unroll
            for (int nd = 0; nd < 8; nd++)
                mma_bf16_16816(o[nd], ph, vbl[nd], o[nd]);
#pragma unroll
            for (int nd = 0; nd < 8; nd++)
                mma_bf16_16816(o[nd], pl, vbh[nd], o[nd]);
        }
    }

    // --- Epilogue: normalize, write merged-head layout ---
    const float inv0 = 1.f / l0, inv1 = 1.f / l1;
    const size_t gr0 = (size_t)b * T_ + qt * 64 + w16 + r4;
#pragma unroll
    for (int nd = 0; nd < 8; nd++) {
        int col = h * D_ + nd * 8 + 2 * t4;
        *(float2*)(att + gr0 * C_ + col) =
            make_float2(o[nd][0] * inv0, o[nd][1] * inv0);
        *(float2*)(att + (gr0 + 8) * C_ + col) =
            make_float2(o[nd][2] * inv1, o[nd][3] * inv1);
    }
}

// ----------------------------------------------------------------------------
// Launch
// ----------------------------------------------------------------------------
extern "C" void kernel_launch(void* const* d_in, const int* in_sizes, int n_in,
                              void* d_out, int out_size)
{
    const float* x     = (const float*)d_in[0];
    // d_in[1] = causal mask (bool) — causality applied analytically, unused
    const float* w_qkv = (const float*)d_in[2];
    const float* w_out = (const float*)d_in[3];
    float* out = (float*)d_out;

    float* qkv_ptr; float* att_ptr;
    cudaGetSymbolAddress((void**)&qkv_ptr, g_qkv);
    cudaGetSymbolAddress((void**)&att_ptr, g_att);

    cudaFuncSetAttribute(flash_attn_tc,
                         cudaFuncAttributeMaxDynamicSharedMemorySize, FLASH_SMEM);
    cudaFuncSetAttribute(gemm_bf16split,
                         cudaFuncAttributeMaxDynamicSharedMemorySize, GEMM_SMEM);

    // 1) QKV projection
    {
        dim3 grid(F3 / GBN, BT / GBM);
        gemm_bf16split<<<grid, 256, GEMM_SMEM>>>(x, w_qkv, qkv_ptr, BT, F3, C_);
    }

    // 2) Fused causal attention (tensor cores)
    {
        dim3 grid(T_ / 64, H_, B_);
        flash_attn_tc<<<grid, 128, FLASH_SMEM>>>(qkv_ptr, att_ptr);
    }

    // 3) Output projection
    {
        dim3 grid(C_ / GBN, BT / GBM);
        gemm_bf16split<<<grid, 256, GEMM_SMEM>>>(att_ptr, w_out, out, BT, C_, C_);
    }
}

// round 9
// speedup vs baseline: 1.8329x; 1.0635x over previous
#include <cuda_runtime.h>
#include <cuda_bf16.h>

// Problem constants
#define B_ 4
#define T_ 2048
#define C_ 1024
#define H_ 16
#define D_ 64
#define BT (B_*T_)          // 8192
#define F3 (3*C_)           // 3072

// ---------------------------------------------------------------------------
// Scratch: bf16 hi/lo planes (uint4 arrays -> 16B alignment for cp.async)
// ---------------------------------------------------------------------------
__device__ uint4 g_xh [(size_t)BT*C_/8],  g_xl [(size_t)BT*C_/8];
__device__ uint4 g_wqh[(size_t)F3*C_/8],  g_wql[(size_t)F3*C_/8];
__device__ uint4 g_woh[(size_t)C_*C_/8],  g_wol[(size_t)C_*C_/8];
__device__ uint4 g_qh [(size_t)BT*F3/8],  g_ql [(size_t)BT*F3/8];   // qkv planes
__device__ uint4 g_ah [(size_t)BT*C_/8],  g_al [(size_t)BT*C_/8];   // att planes

// ---------------------------------------------------------------------------
// Helpers
// ---------------------------------------------------------------------------
__device__ __forceinline__ void mma_bf16_16816(float* d, const unsigned* a,
                                               const unsigned* b, const float* c)
{
    asm volatile(
        "mma.sync.aligned.m16n8k16.row.col.f32.bf16.bf16.f32 "
        "{%0,%1,%2,%3}, {%4,%5,%6,%7}, {%8,%9}, {%10,%11,%12,%13};\n"
        : "=f"(d[0]), "=f"(d[1]), "=f"(d[2]), "=f"(d[3])
        : "r"(a[0]), "r"(a[1]), "r"(a[2]), "r"(a[3]),
          "r"(b[0]), "r"(b[1]),
          "f"(c[0]), "f"(c[1]), "f"(c[2]), "f"(c[3]));
}

__device__ __forceinline__ unsigned pack_bf16(float x0, float x1)
{
    __nv_bfloat162 t = __floats2bfloat162_rn(x0, x1);
    return *(unsigned*)&t;
}

__device__ __forceinline__ void split2(float x0, float x1, unsigned& hi, unsigned& lo)
{
    __nv_bfloat16 h0 = __float2bfloat16_rn(x0);
    __nv_bfloat16 h1 = __float2bfloat16_rn(x1);
    __nv_bfloat162 hv; hv.x = h0; hv.y = h1;
    hi = *(unsigned*)&hv;
    lo = pack_bf16(x0 - __bfloat162float(h0), x1 - __bfloat162float(h1));
}

__device__ __forceinline__ unsigned smem_u32(const void* p)
{
    unsigned a;
    asm("{ .reg .u64 t; cvta.to.shared.u64 t, %1; cvt.u32.u64 %0, t; }"
        : "=r"(a) : "l"(p));
    return a;
}

// ---------------------------------------------------------------------------
// Elementwise fp32 -> (hi,lo) bf16 planes
// ---------------------------------------------------------------------------
__global__ void split_pass(const float* __restrict__ src,
                           unsigned* __restrict__ hi, unsigned* __restrict__ lo,
                           int n2)
{
    int i = blockIdx.x * blockDim.x + threadIdx.x;
    if (i < n2) {
        float2 v = ((const float2*)src)[i];
        unsigned h, l;
        split2(v.x, v.y, h, l);
        hi[i] = h; lo[i] = l;
    }
}

// ===========================================================================
// bf16 hi/lo-plane GEMM: C = A[M,K] @ B[N,K]^T with 3-term split accumulation.
// cp.async double-buffered, 128x128x32 tile, 8 warps (2x4), warp 64x32.
// ===========================================================================
#define GBK 32
#define GPS 2560            // plane size in u32 (128*20)
#define GEMM_SMEM (2*4*GPS*4)

template<bool SPLIT_OUT>
__global__ __launch_bounds__(256, 2)
void gemm_async(const uint4* __restrict__ Ah4, const uint4* __restrict__ Al4,
                const uint4* __restrict__ Bh4, const uint4* __restrict__ Bl4,
                float* __restrict__ Cf,
                unsigned* __restrict__ Chi, unsigned* __restrict__ Clo,
                int M, int N, int K)
{
    extern __shared__ unsigned sm_u[];
    const unsigned smem_base = smem_u32(sm_u);

    const int tid  = threadIdx.x;
    const int lane = tid & 31;
    const int wid  = tid >> 5;
    const int wm   = (wid >> 2) * 64;
    const int wn   = (wid & 3) * 32;
    const int m0   = blockIdx.y * 128;
    const int n0   = blockIdx.x * 128;
    const int r4   = lane >> 2;
    const int t4   = lane & 3;
    const int K8   = K >> 3;            // uint4 per gmem row

    float acc[4][4][4];
#pragma unroll
    for (int i = 0; i < 4; i++)
#pragma unroll
        for (int j = 0; j < 4; j++)
#pragma unroll
            for (int r = 0; r < 4; r++) acc[i][j][r] = 0.f;

    auto load_slice = [&](int buf, int k0) {
        const int k4 = k0 >> 3;
#pragma unroll
        for (int i = 0; i < 8; i++) {
            const int p   = i >> 1;                    // plane 0..3
            const int row = (i & 1) * 64 + (tid >> 2);
            const int c   = tid & 3;
            const uint4* src;
            size_t g;
            if (p < 2) { src = (p == 0) ? Ah4 : Al4; g = (size_t)(m0 + row) * K8 + k4 + c; }
            else       { src = (p == 2) ? Bh4 : Bl4; g = (size_t)(n0 + row) * K8 + k4 + c; }
            const unsigned dst = smem_base + ((buf * 4 + p) * GPS) * 4 + row * 80 + c * 16;
            asm volatile("cp.async.cg.shared.global [%0], [%1], 16;"
                         :: "r"(dst), "l"(src + g));
        }
        asm volatile("cp.async.commit_group;");
    };

    load_slice(0, 0);

    int buf = 0;
    const int NS = K / GBK;
    for (int s = 0; s < NS; s++) {
        if (s + 1 < NS) {
            load_slice(buf ^ 1, (s + 1) * GBK);
            asm volatile("cp.async.wait_group 1;");
        } else {
            asm volatile("cp.async.wait_group 0;");
        }
        __syncthreads();

        const unsigned* AH = sm_u + (buf * 4 + 0) * GPS;
        const unsigned* AL = sm_u + (buf * 4 + 1) * GPS;
        const unsigned* BH = sm_u + (buf * 4 + 2) * GPS;
        const unsigned* BL = sm_u + (buf * 4 + 3) * GPS;

#pragma unroll
        for (int ks = 0; ks < 2; ks++) {
            // hi fragments first; lo fragments loaded late to shrink live range
            unsigned ah[4][4], bh[4][2];
#pragma unroll
            for (int mt = 0; mt < 4; mt++) {
                int w = (wm + mt * 16 + r4) * 20 + ks * 8 + t4;
                ah[mt][0] = AH[w];       ah[mt][1] = AH[w + 160];
                ah[mt][2] = AH[w + 4];   ah[mt][3] = AH[w + 164];
            }
#pragma unroll
            for (int nt = 0; nt < 4; nt++) {
                int w = (wn + nt * 8 + r4) * 20 + ks * 8 + t4;
                bh[nt][0] = BH[w];  bh[nt][1] = BH[w + 4];
            }
            // term 1: hi*hi
#pragma unroll
            for (int mt = 0; mt < 4; mt++)
#pragma unroll
                for (int nt = 0; nt < 4; nt++)
                    mma_bf16_16816(acc[mt][nt], ah[mt], bh[nt], acc[mt][nt]);

            // term 2: hi*lo
            unsigned bl[4][2];
#pragma unroll
            for (int nt = 0; nt < 4; nt++) {
                int w = (wn + nt * 8 + r4) * 20 + ks * 8 + t4;
                bl[nt][0] = BL[w];  bl[nt][1] = BL[w + 4];
            }
#pragma unroll
            for (int mt = 0; mt < 4; mt++)
#pragma unroll
                for (int nt = 0; nt < 4; nt++)
                    mma_bf16_16816(acc[mt][nt], ah[mt], bl[nt], acc[mt][nt]);

            // term 3: lo*hi
            unsigned al[4][4];
#pragma unroll
            for (int mt = 0; mt < 4; mt++) {
                int w = (wm + mt * 16 + r4) * 20 + ks * 8 + t4;
                al[mt][0] = AL[w];       al[mt][1] = AL[w + 160];
                al[mt][2] = AL[w + 4];   al[mt][3] = AL[w + 164];
            }
#pragma unroll
            for (int mt = 0; mt < 4; mt++)
#pragma unroll
                for (int nt = 0; nt < 4; nt++)
                    mma_bf16_16816(acc[mt][nt], al[mt], bh[nt], acc[mt][nt]);
        }
        __syncthreads();   // all warps done with buf before it is overwritten
        buf ^= 1;
    }

#pragma unroll
    for (int mt = 0; mt < 4; mt++) {
        int row0 = m0 + wm + mt * 16 + r4;
#pragma unroll
        for (int nt = 0; nt < 4; nt++) {
            int col = n0 + wn + nt * 8 + t4 * 2;
            if (SPLIT_OUT) {
                unsigned h, l;
                int cu = col >> 1, N2 = N >> 1;
                split2(acc[mt][nt][0], acc[mt][nt][1], h, l);
                Chi[(size_t)row0 * N2 + cu] = h;
                Clo[(size_t)row0 * N2 + cu] = l;
                split2(acc[mt][nt][2], acc[mt][nt][3], h, l);
                Chi[(size_t)(row0 + 8) * N2 + cu] = h;
                Clo[(size_t)(row0 + 8) * N2 + cu] = l;
            } else {
                *(float2*)(Cf + (size_t)row0 * N + col) =
                    make_float2(acc[mt][nt][0], acc[mt][nt][1]);
                *(float2*)(Cf + (size_t)(row0 + 8) * N + col) =
                    make_float2(acc[mt][nt][2], acc[mt][nt][3]);
            }
        }
    }
}

// ===========================================================================
// Tensor-core causal flash attention over pre-split bf16 hi/lo qkv planes.
// K/V tiles double-buffered via cp.async (same commit/wait pattern as GEMM).
// Block: 128 threads (4 warps), 64 queries x D=64, key tiles of 64.
// smem: Q(2 planes) + 2 bufs x {Kh,Kl,Vh,Vl} = 10 planes x 2304 u32 = 92,160 B.
// ===========================================================================
#define FPLN 2304                 // plane size in u32 (64 rows * 36)
#define FP_QH 0
#define FP_QL FPLN
#define FP_KV (2*FPLN)            // K/V double buffers start here
#define FLASH_SMEM (10*FPLN*4)    // 92,160 B

__global__ __launch_bounds__(128, 2)
void flash_attn_tc(const uint4* __restrict__ qkv_h, const uint4* __restrict__ qkv_l,
                   unsigned* __restrict__ att_h, unsigned* __restrict__ att_l)
{
    extern __shared__ unsigned smf[];
    const unsigned smem_base = smem_u32(smf);

    const int qt = 31 - blockIdx.x;       // heavy tiles first
    const int h  = blockIdx.y, b = blockIdx.z;
    const int tid  = threadIdx.x;
    const int lane = tid & 31;
    const int wid  = tid >> 5;
    const int w16  = wid * 16;
    const int r4   = lane >> 2;
    const int t4   = lane & 3;

    const float SC = 0.125f * 1.44269504088896340736f;  // 1/sqrt(D) * log2(e)
    const int F38  = F3 / 8;                             // uint4 per qkv row
    const size_t brow = (size_t)b * T_;

    // cp.async one K/V tile (4 planes, 32 KB) into buffer `buf`
    auto load_tile = [&](int buf, int kt2) {
        const size_t t0 = (brow + kt2 * 64) * F38;
        const size_t kOff = t0 + 128 + h * 8;   // K block: col C_  + h*64
        const size_t vOff = t0 + 256 + h * 8;   // V block: col 2C_ + h*64
#pragma unroll
        for (int it = 0; it < 16; it++) {
            int idx = it * 128 + tid;           // 0..2047
            int p = idx >> 9;                   // 0:Kh 1:Kl 2:Vh 3:Vl
            int r = (idx >> 3) & 63;
            int c = idx & 7;
            const uint4* src = (p & 1) ? qkv_l : qkv_h;
            size_t g = ((p < 2) ? kOff : vOff) + (size_t)r * F38 + c;
            unsigned dst = smem_base + (FP_KV + (buf * 4 + p) * FPLN + r * 36 + c * 4) * 4;
            asm volatile("cp.async.cg.shared.global [%0], [%1], 16;"
                         :: "r"(dst), "l"(src + g));
        }
        asm volatile("cp.async.commit_group;");
    };

    // --- Copy Q hi/lo tile into smem (synchronous) + prefetch tile 0 ---
    {
        const size_t q0 = (brow + qt * 64) * F38 + h * 8;
#pragma unroll
        for (int it = 0; it < 8; it++) {
            int idx = it * 128 + tid;           // 0..1023
            int p = idx >> 9;                   // 0: hi, 1: lo
            int r = (idx >> 3) & 63;
            int c = idx & 7;
            uint4 v = (p == 0 ? qkv_h : qkv_l)[q0 + (size_t)r * F38 + c];
            *(uint4*)(smf + (p == 0 ? FP_QH : FP_QL) + r * 36 + c * 4) = v;
        }
    }
    load_tile(0, 0);
    __syncthreads();

    // --- Hoist Q fragments (loop-invariant) ---
    unsigned qh[4][4], ql[4][4];
#pragma unroll
    for (int ks = 0; ks < 4; ks++) {
        int w = (w16 + r4) * 36 + ks * 8 + t4;
        qh[ks][0] = smf[FP_QH + w];        qh[ks][1] = smf[FP_QH + w + 288];
        qh[ks][2] = smf[FP_QH + w + 4];    qh[ks][3] = smf[FP_QH + w + 292];
        ql[ks][0] = smf[FP_QL + w];        ql[ks][1] = smf[FP_QL + w + 288];
        ql[ks][2] = smf[FP_QL + w + 4];    ql[ks][3] = smf[FP_QL + w + 292];
    }

    float m0 = -1e30f, m1 = -1e30f, l0 = 0.f, l1 = 0.f;
    float o[8][4];
#pragma unroll
    for (int nd = 0; nd < 8; nd++)
#pragma unroll
        for (int e = 0; e < 4; e++) o[nd][e] = 0.f;

    const int qrow0 = qt * 64 + w16 + r4;
    const int qrow1 = qrow0 + 8;

    int fbuf = 0;
    for (int kt = 0; kt <= qt; kt++) {
        if (kt + 1 <= qt) {
            load_tile(fbuf ^ 1, kt + 1);
            asm volatile("cp.async.wait_group 1;");
        } else {
            asm volatile("cp.async.wait_group 0;");
        }
        __syncthreads();

        const int KH = FP_KV + (fbuf * 4 + 0) * FPLN;
        const int KL = FP_KV + (fbuf * 4 + 1) * FPLN;
        const unsigned vh_base = smem_base + (FP_KV + (fbuf * 4 + 2) * FPLN) * 4
                               + (lane & 15) * 144;
        const unsigned vl_base = vh_base + FPLN * 4;

        // --- S = Q K^T (3-term split, term-major) ---
        float s[8][4];
#pragma unroll
        for (int j = 0; j < 8; j++)
#pragma unroll
            for (int e = 0; e < 4; e++) s[j][e] = 0.f;

#pragma unroll
        for (int ks = 0; ks < 4; ks++) {
            unsigned bh[8][2], bl[8][2];
#pragma unroll
            for (int j = 0; j < 8; j++) {
                int w = (j * 8 + r4) * 36 + ks * 8 + t4;
                bh[j][0] = smf[KH + w];  bh[j][1] = smf[KH + w + 4];
                bl[j][0] = smf[KL + w];  bl[j][1] = smf[KL + w + 4];
            }
#pragma unroll
            for (int j = 0; j < 8; j++)
                mma_bf16_16816(s[j], qh[ks], bh[j], s[j]);
#pragma unroll
            for (int j = 0; j < 8; j++)
                mma_bf16_16816(s[j], qh[ks], bl[j], s[j]);
#pragma unroll
            for (int j = 0; j < 8; j++)
                mma_bf16_16816(s[j], ql[ks], bh[j], s[j]);
        }

        // scale into exp2 domain
#pragma unroll
        for (int j = 0; j < 8; j++)
#pragma unroll
            for (int e = 0; e < 4; e++) s[j][e] *= SC;

        // --- Causal mask (diagonal tile only) ---
        if (kt == qt) {
#pragma unroll
            for (int j = 0; j < 8; j++) {
                int kc = kt * 64 + j * 8 + 2 * t4;
                if (kc     > qrow0) s[j][0] = -1e30f;
                if (kc + 1 > qrow0) s[j][1] = -1e30f;
                if (kc     > qrow1) s[j][2] = -1e30f;
                if (kc + 1 > qrow1) s[j][3] = -1e30f;
            }
        }

        // --- Online softmax (exp2 domain) ---
        float mx0 = -1e30f, mx1 = -1e30f;
#pragma unroll
        for (int j = 0; j < 8; j++) {
            mx0 = fmaxf(mx0, fmaxf(s[j][0], s[j][1]));
            mx1 = fmaxf(mx1, fmaxf(s[j][2], s[j][3]));
        }
        mx0 = fmaxf(mx0, __shfl_xor_sync(0xffffffffu, mx0, 1));
        mx0 = fmaxf(mx0, __shfl_xor_sync(0xffffffffu, mx0, 2));
        mx1 = fmaxf(mx1, __shfl_xor_sync(0xffffffffu, mx1, 1));
        mx1 = fmaxf(mx1, __shfl_xor_sync(0xffffffffu, mx1, 2));

        float nm0 = fmaxf(m0, mx0), nm1 = fmaxf(m1, mx1);
        float c0 = exp2f(m0 - nm0), c1 = exp2f(m1 - nm1);
        m0 = nm0; m1 = nm1;

        float sum0 = 0.f, sum1 = 0.f;
#pragma unroll
        for (int j = 0; j < 8; j++) {
            s[j][0] = exp2f(s[j][0] - m0);
            s[j][1] = exp2f(s[j][1] - m0);
            s[j][2] = exp2f(s[j][2] - m1);
            s[j][3] = exp2f(s[j][3] - m1);
            sum0 += s[j][0] + s[j][1];
            sum1 += s[j][2] + s[j][3];
        }
        sum0 += __shfl_xor_sync(0xffffffffu, sum0, 1);
        sum0 += __shfl_xor_sync(0xffffffffu, sum0, 2);
        sum1 += __shfl_xor_sync(0xffffffffu, sum1, 1);
        sum1 += __shfl_xor_sync(0xffffffffu, sum1, 2);
        l0 = l0 * c0 + sum0;
        l1 = l1 * c1 + sum1;

#pragma unroll
        for (int nd = 0; nd < 8; nd++) {
            o[nd][0] *= c0; o[nd][1] *= c0;
            o[nd][2] *= c1; o[nd][3] *= c1;
        }

        // --- O += P V (3-term split, term-major) ---
#pragma unroll
        for (int kp = 0; kp < 4; kp++) {
            const int j0 = 2 * kp, j1 = 2 * kp + 1;
            unsigned ph[4], pl[4];
            split2(s[j0][0], s[j0][1], ph[0], pl[0]);
            split2(s[j0][2], s[j0][3], ph[1], pl[1]);
            split2(s[j1][0], s[j1][1], ph[2], pl[2]);
            split2(s[j1][2], s[j1][3], ph[3], pl[3]);

            unsigned vbh[8][2], vbl[8][2];
#pragma unroll
            for (int nd = 0; nd < 8; nd++) {
                asm volatile("ldmatrix.sync.aligned.m8n8.x2.trans.shared.b16 {%0,%1}, [%2];"
                             : "=r"(vbh[nd][0]), "=r"(vbh[nd][1])
                             : "r"(vh_base + kp * 16 * 144 + nd * 16));
                asm volatile("ldmatrix.sync.aligned.m8n8.x2.trans.shared.b16 {%0,%1}, [%2];"
                             : "=r"(vbl[nd][0]), "=r"(vbl[nd][1])
                             : "r"(vl_base + kp * 16 * 144 + nd * 16));
            }
#pragma unroll
            for (int nd = 0; nd < 8; nd++)
                mma_bf16_16816(o[nd], ph, vbh[nd], o[nd]);
#pragma unroll
            for (int nd = 0; nd < 8; nd++)
                mma_bf16_16816(o[nd], ph, vbl[nd], o[nd]);
#pragma unroll
            for (int nd = 0; nd < 8; nd++)
                mma_bf16_16816(o[nd], pl, vbh[nd], o[nd]);
        }

        __syncthreads();   // all warps done with fbuf before next issue overwrites it
        fbuf ^= 1;
    }

    // --- Epilogue: normalize, split, write att hi/lo planes ---
    const float inv0 = 1.f / l0, inv1 = 1.f / l1;
    const size_t gr0 = brow + qt * 64 + w16 + r4;
    const int C2 = C_ >> 1;
#pragma unroll
    for (int nd = 0; nd < 8; nd++) {
        int cu = h * 32 + nd * 4 + t4;
        unsigned hh, ll;
        split2(o[nd][0] * inv0, o[nd][1] * inv0, hh, ll);
        att_h[gr0 * C2 + cu] = hh;
        att_l[gr0 * C2 + cu] = ll;
        split2(o[nd][2] * inv1, o[nd][3] * inv1, hh, ll);
        att_h[(gr0 + 8) * C2 + cu] = hh;
        att_l[(gr0 + 8) * C2 + cu] = ll;
    }
}

// ---------------------------------------------------------------------------
// Launch
// ---------------------------------------------------------------------------
extern "C" void kernel_launch(void* const* d_in, const int* in_sizes, int n_in,
                              void* d_out, int out_size)
{
    const float* x     = (const float*)d_in[0];
    // d_in[1] = causal mask (bool) — applied analytically, unused
    const float* w_qkv = (const float*)d_in[2];
    const float* w_out = (const float*)d_in[3];
    float* out = (float*)d_out;

    uint4 *xh, *xl, *wqh, *wql, *woh, *wol, *qh, *ql, *ah, *al;
    cudaGetSymbolAddress((void**)&xh,  g_xh);  cudaGetSymbolAddress((void**)&xl,  g_xl);
    cudaGetSymbolAddress((void**)&wqh, g_wqh); cudaGetSymbolAddress((void**)&wql, g_wql);
    cudaGetSymbolAddress((void**)&woh, g_woh); cudaGetSymbolAddress((void**)&wol, g_wol);
    cudaGetSymbolAddress((void**)&qh,  g_qh);  cudaGetSymbolAddress((void**)&ql,  g_ql);
    cudaGetSymbolAddress((void**)&ah,  g_ah);  cudaGetSymbolAddress((void**)&al,  g_al);

    cudaFuncSetAttribute(gemm_async<true>,
                         cudaFuncAttributeMaxDynamicSharedMemorySize, GEMM_SMEM);
    cudaFuncSetAttribute(gemm_async<false>,
                         cudaFuncAttributeMaxDynamicSharedMemorySize, GEMM_SMEM);
    cudaFuncSetAttribute(flash_attn_tc,
                         cudaFuncAttributeMaxDynamicSharedMemorySize, FLASH_SMEM);

    // 0) Pre-split inputs into bf16 hi/lo planes
    split_pass<<<BT*C_/2/256, 256>>>(x,     (unsigned*)xh,  (unsigned*)xl,  BT*C_/2);
    split_pass<<<F3*C_/2/256, 256>>>(w_qkv, (unsigned*)wqh, (unsigned*)wql, F3*C_/2);
    split_pass<<<C_*C_/2/256, 256>>>(w_out, (unsigned*)woh, (unsigned*)wol, C_*C_/2);

    // 1) QKV projection -> qkv hi/lo planes
    {
        dim3 grid(F3 / 128, BT / 128);
        gemm_async<true><<<grid, 256, GEMM_SMEM>>>(
            xh, xl, wqh, wql, nullptr, (unsigned*)qh, (unsigned*)ql, BT, F3, C_);
    }

    // 2) Fused causal attention -> att hi/lo planes
    {
        dim3 grid(T_ / 64, H_, B_);
        flash_attn_tc<<<grid, 128, FLASH_SMEM>>>(qh, ql, (unsigned*)ah, (unsigned*)al);
    }

    // 3) Output projection -> fp32 out
    {
        dim3 grid(C_ / 128, BT / 128);
        gemm_async<false><<<grid, 256, GEMM_SMEM>>>(
            ah, al, woh, wol, out, nullptr, nullptr, BT, C_, C_);
    }
}